// round 17
// baseline (speedup 1.0000x reference)
#include <cuda_runtime.h>
#include <math.h>
#include <stdint.h>

#define B_ 1024
#define T_ 16
#define D_ 1024
#define H_ 2048
#define O_ 1024
#define LIST_MAX (1 << 20)

// ==================== device globals ========================================
__device__ float r17_Wfused[D_ * H_];
__device__ float r17_bfused[H_];
__device__ float r17_WencT[H_ * H_], r17_WrecT[H_ * H_];
__device__ float r17_preall[B_ * T_ * H_];
__device__ float r17_sall[B_ * T_ * H_];
__device__ float r17_recall[B_ * T_ * H_];
__device__ float r17_ctxall[B_ * T_ * H_];
__device__ float r17_gatedall[B_ * T_ * H_];
__device__ float r17_encall[B_ * T_ * H_];
__device__ float r17_attrA[B_ * H_], r17_attrB[B_ * H_];
__device__ float r17_spk[B_ * H_];
__device__ int   r17_cnt[T_];
__device__ int   r17_list[LIST_MAX];

// ==================== helpers ===============================================
__device__ __forceinline__ uint32_t r17_smem_u32(const void* p) {
    uint32_t a;
    asm("{ .reg .u64 t; cvta.to.shared.u64 t, %1; cvt.u32.u64 %0, t; }" : "=r"(a) : "l"(p));
    return a;
}
__device__ __forceinline__ void r17_cp16(uint32_t dst, const void* src) {
    asm volatile("cp.async.cg.shared.global [%0], [%1], 16;" :: "r"(dst), "l"(src));
}

// ==================== fp32 SGEMM, pipelined, fused epilogues =================
// mode 0: C = alpha*acc + bias1 (+bias2) (+Cin row-strided)
// mode 1: p = acc + bias1; g = sigmoid(p); C = g*ctx + (1-g)*rec
// mode 2: cur = acc + Cin; LIF vs attr_in -> C(=attr_out), spk, near-threshold list
#define BM 128
#define BN 128
#define BK 16
#define STG_F (BK * BM + BK * BN)   // floats per stage (A transposed + B)

__global__ void __launch_bounds__(256) r17_sgemm(
    int mode,
    const float* __restrict__ A1, int lda1, const float* __restrict__ B1,
    const float* __restrict__ bias1, const float* __restrict__ bias2,
    const float* __restrict__ Cin, long ldcin,
    const float* __restrict__ aux1,   // mode1: ctx ; mode2: attr_in
    const float* __restrict__ aux2,   // mode1: rec ; mode2: spk
    int* __restrict__ cnt_t, int* __restrict__ list,
    float* __restrict__ C, int ldc, int M, int N, int K, float alpha)
{
    __shared__ float smem[2 * STG_F];
    const uint32_t sb = r17_smem_u32(smem);
    const int bm = blockIdx.y * BM, bn = blockIdx.x * BN;
    const int tid = threadIdx.x, tr = tid / 16, tc = tid % 16;
    const int a_r = tid / 4, a_c = (tid % 4) * 4;
    const int b_r = tid / 32, b_c = (tid % 32) * 4;

    float acc[8][8];
#pragma unroll
    for (int i = 0; i < 8; i++)
#pragma unroll
        for (int j = 0; j < 8; j++) acc[i][j] = 0.0f;

    // stage s base pointers
    float* As[2] = { smem,            smem + STG_F };
    float* Bs[2] = { smem + BK * BM,  smem + STG_F + BK * BM };

    // prologue: tile 0 -> stage 0
    {
#pragma unroll
        for (int i = 0; i < 2; i++) {
            int r = a_r + i * 64;
            float4 v = *(const float4*)(A1 + (long)(bm + r) * lda1 + a_c);
            As[0][(a_c + 0) * BM + r] = v.x;
            As[0][(a_c + 1) * BM + r] = v.y;
            As[0][(a_c + 2) * BM + r] = v.z;
            As[0][(a_c + 3) * BM + r] = v.w;
        }
        const uint32_t bbase = sb + (uint32_t)(BK * BM) * 4u;
#pragma unroll
        for (int i = 0; i < 2; i++) {
            int r = b_r + i * 8;
            r17_cp16(bbase + (uint32_t)(r * BN + b_c) * 4u,
                     B1 + (long)r * N + bn + b_c);
        }
        asm volatile("cp.async.commit_group;" ::: "memory");
        asm volatile("cp.async.wait_group 0;" ::: "memory");
        __syncthreads();
    }

    const int ntiles = K / BK;
    for (int kt = 0; kt < ntiles; kt++) {
        const int s = kt & 1;
        float4 nextA[2];
        const bool more = (kt + 1 < ntiles);
        if (more) {
            const int k0 = (kt + 1) * BK;
#pragma unroll
            for (int i = 0; i < 2; i++) {
                int r = a_r + i * 64;
                nextA[i] = *(const float4*)(A1 + (long)(bm + r) * lda1 + k0 + a_c);
            }
            const uint32_t bbase = sb + (uint32_t)((s ^ 1) * STG_F + BK * BM) * 4u;
#pragma unroll
            for (int i = 0; i < 2; i++) {
                int r = b_r + i * 8;
                r17_cp16(bbase + (uint32_t)(r * BN + b_c) * 4u,
                         B1 + (long)(k0 + r) * N + bn + b_c);
            }
            asm volatile("cp.async.commit_group;" ::: "memory");
        }

        const float* Asp = As[s];
        const float* Bsp = Bs[s];
#pragma unroll
        for (int kk = 0; kk < BK; kk++) {
            float4 a0 = *(const float4*)&Asp[kk * BM + tr * 8];
            float4 a1 = *(const float4*)&Asp[kk * BM + tr * 8 + 4];
            float4 b0 = *(const float4*)&Bsp[kk * BN + tc * 8];
            float4 b1 = *(const float4*)&Bsp[kk * BN + tc * 8 + 4];
            float a[8] = {a0.x, a0.y, a0.z, a0.w, a1.x, a1.y, a1.z, a1.w};
            float b[8] = {b0.x, b0.y, b0.z, b0.w, b1.x, b1.y, b1.z, b1.w};
#pragma unroll
            for (int i = 0; i < 8; i++)
#pragma unroll
                for (int j = 0; j < 8; j++)
                    acc[i][j] = fmaf(a[i], b[j], acc[i][j]);
        }

        if (more) {
            float* Ad = As[s ^ 1];
#pragma unroll
            for (int i = 0; i < 2; i++) {
                int r = a_r + i * 64;
                Ad[(a_c + 0) * BM + r] = nextA[i].x;
                Ad[(a_c + 1) * BM + r] = nextA[i].y;
                Ad[(a_c + 2) * BM + r] = nextA[i].z;
                Ad[(a_c + 3) * BM + r] = nextA[i].w;
            }
            asm volatile("cp.async.wait_group 0;" ::: "memory");
            __syncthreads();
        }
    }

    // ==================== epilogue =====================
    const int row0 = bm + tr * 8, col0 = bn + tc * 8;

    if (mode == 0) {
        float bias[8];
#pragma unroll
        for (int j = 0; j < 8; j++) {
            float v = bias1 ? bias1[col0 + j] : 0.0f;
            if (bias2) v += bias2[col0 + j];
            bias[j] = v;
        }
#pragma unroll
        for (int i = 0; i < 8; i++) {
            float c[8];
#pragma unroll
            for (int j = 0; j < 8; j++) c[j] = alpha * acc[i][j] + bias[j];
            if (Cin) {
                float4 ci0 = *(const float4*)(Cin + (long)(row0 + i) * ldcin + col0);
                float4 ci1 = *(const float4*)(Cin + (long)(row0 + i) * ldcin + col0 + 4);
                c[0] += ci0.x; c[1] += ci0.y; c[2] += ci0.z; c[3] += ci0.w;
                c[4] += ci1.x; c[5] += ci1.y; c[6] += ci1.z; c[7] += ci1.w;
            }
            *(float4*)(C + (long)(row0 + i) * ldc + col0)     = make_float4(c[0], c[1], c[2], c[3]);
            *(float4*)(C + (long)(row0 + i) * ldc + col0 + 4) = make_float4(c[4], c[5], c[6], c[7]);
        }
    } else if (mode == 1) {
        // gated fusion: C = sigmoid(acc + bg) * ctx + (1-g) * rec
        float bias[8];
#pragma unroll
        for (int j = 0; j < 8; j++) bias[j] = bias1[col0 + j];
#pragma unroll
        for (int i = 0; i < 8; i++) {
            const long ro = (long)(row0 + i) * ldc + col0;
            float4 cx0 = *(const float4*)(aux1 + ro);
            float4 cx1 = *(const float4*)(aux1 + ro + 4);
            float4 rc0 = *(const float4*)(aux2 + ro);
            float4 rc1 = *(const float4*)(aux2 + ro + 4);
            float cx[8] = {cx0.x, cx0.y, cx0.z, cx0.w, cx1.x, cx1.y, cx1.z, cx1.w};
            float rc[8] = {rc0.x, rc0.y, rc0.z, rc0.w, rc1.x, rc1.y, rc1.z, rc1.w};
            float c[8];
#pragma unroll
            for (int j = 0; j < 8; j++) {
                float p = acc[i][j] + bias[j];
                float g = 1.0f / (1.0f + expf(-p));
                c[j] = g * cx[j] + (1.0f - g) * rc[j];
            }
            *(float4*)(C + ro)     = make_float4(c[0], c[1], c[2], c[3]);
            *(float4*)(C + ro + 4) = make_float4(c[4], c[5], c[6], c[7]);
        }
    } else {
        // LIF fusion: cur = acc + Cin ; v, spike, mark; C = attr_out
#pragma unroll
        for (int i = 0; i < 8; i++) {
            const long ro = (long)(row0 + i) * ldc + col0;
            float4 ci0 = *(const float4*)(Cin + (long)(row0 + i) * ldcin + col0);
            float4 ci1 = *(const float4*)(Cin + (long)(row0 + i) * ldcin + col0 + 4);
            float4 ai0 = *(const float4*)(aux1 + ro);
            float4 ai1 = *(const float4*)(aux1 + ro + 4);
            float4 sp0 = *(const float4*)(aux2 + ro);
            float4 sp1 = *(const float4*)(aux2 + ro + 4);
            float cu[8] = {ci0.x, ci0.y, ci0.z, ci0.w, ci1.x, ci1.y, ci1.z, ci1.w};
            float av[8] = {ai0.x, ai0.y, ai0.z, ai0.w, ai1.x, ai1.y, ai1.z, ai1.w};
            float sv[8] = {sp0.x, sp0.y, sp0.z, sp0.w, sp1.x, sp1.y, sp1.z, sp1.w};
#pragma unroll
            for (int j = 0; j < 8; j++) {
                float cur = acc[i][j] + cu[j];
                float v = av[j] + (cur - av[j]) * 0.5f;
                float s = (v > 1.0f) ? 1.0f : 0.0f;
                if (fabsf(v - 1.0f) < 1e-4f) {
                    int idx = atomicAdd(cnt_t, 1);
                    if (idx < LIST_MAX)
                        list[idx] = (int)(((ro + j) << 1) | (int)s);
                }
                av[j] = v - s;
                sv[j] += s;
            }
            *(float4*)(C + ro)     = make_float4(av[0], av[1], av[2], av[3]);
            *(float4*)(C + ro + 4) = make_float4(av[4], av[5], av[6], av[7]);
            *(float4*)((float*)aux2 + ro)     = make_float4(sv[0], sv[1], sv[2], sv[3]);
            *(float4*)((float*)aux2 + ro + 4) = make_float4(sv[4], sv[5], sv[6], sv[7]);
        }
    }
}

// bfused[n] = bp @ Wfc + bfc
__global__ void __launch_bounds__(256) r17_bfused_kernel(
    const float* __restrict__ bp, const float* __restrict__ Wfc,
    const float* __restrict__ bfc, float* __restrict__ out)
{
    const int n = blockIdx.x * 256 + threadIdx.x;
    float a0 = 0.f, a1 = 0.f, a2 = 0.f, a3 = 0.f;
    for (int k = 0; k < H_; k += 4) {
        a0 = fmaf(bp[k + 0], Wfc[(long)(k + 0) * H_ + n], a0);
        a1 = fmaf(bp[k + 1], Wfc[(long)(k + 1) * H_ + n], a1);
        a2 = fmaf(bp[k + 2], Wfc[(long)(k + 2) * H_ + n], a2);
        a3 = fmaf(bp[k + 3], Wfc[(long)(k + 3) * H_ + n], a3);
    }
    out[n] = ((a0 + a1) + (a2 + a3)) + bfc[n];
}

// WT[n][k] = W[k][n]
__global__ void __launch_bounds__(256) r17_transpose_kernel(
    const float* __restrict__ W, float* __restrict__ WT, int K, int N)
{
    __shared__ float tile[32][33];
    const int n0 = blockIdx.x * 32, k0 = blockIdx.y * 32;
    const int tx = threadIdx.x & 31, ty = threadIdx.x >> 5;
    for (int i = ty; i < 32; i += 8)
        tile[i][tx] = W[(long)(k0 + i) * N + n0 + tx];
    __syncthreads();
    for (int i = ty; i < 32; i += 8)
        WT[(long)(n0 + i) * K + k0 + tx] = tile[tx][i];
}

// ==================== rec chain =============================================
__inline__ __device__ float r17_warpsum(float v) {
#pragma unroll
    for (int o = 16; o > 0; o >>= 1) v += __shfl_xor_sync(0xffffffffu, v, o);
    return v;
}

__global__ void __launch_bounds__(256) r17_chain_kernel(
    const float* __restrict__ preall, float* __restrict__ recall,
    float* __restrict__ ctxall, float* __restrict__ sall,
    const float* __restrict__ gamma, const float* __restrict__ beta)
{
    const int b = blockIdx.x;
    __shared__ float sh[16];
    const int warp = threadIdx.x >> 5, lane = threadIdx.x & 31;

    float rec[8];
#pragma unroll
    for (int i = 0; i < 8; i++) rec[i] = 0.0f;

    for (int t = 0; t < T_; t++) {
        const long base = ((long)b * T_ + t) * H_;
        float sum = 0.f, sumsq = 0.f;
#pragma unroll
        for (int i = 0; i < 8; i++) {
            int h = threadIdx.x + i * 256;
            float u = tanhf(preall[base + h]);
            float nr = 0.9f * rec[i] + 0.1f * u;
            rec[i] = nr;
            sum += nr; sumsq += nr * nr;
        }
        float w1 = r17_warpsum(sum), w2 = r17_warpsum(sumsq);
        if (lane == 0) { sh[warp] = w1; sh[8 + warp] = w2; }
        __syncthreads();
        if (threadIdx.x == 0) {
            float a = 0.f, c = 0.f;
#pragma unroll
            for (int i = 0; i < 8; i++) { a += sh[i]; c += sh[8 + i]; }
            sh[0] = a; sh[8] = c;
        }
        __syncthreads();
        const float mean = sh[0] * (1.0f / H_);
        const float var  = sh[8] * (1.0f / H_) - mean * mean;
        const float inv  = rsqrtf(var + 1e-5f);
#pragma unroll
        for (int i = 0; i < 8; i++) {
            int h = threadIdx.x + i * 256;
            float c = (rec[i] - mean) * inv * gamma[h] + beta[h];
            recall[base + h] = rec[i];
            ctxall[base + h] = c;
            sall[base + h]   = c + rec[i];
        }
        __syncthreads();
    }
}

// ==================== cooperative fp64 refine ================================
__global__ void __launch_bounds__(256) r17_refine_kernel(
    const int* __restrict__ cnt_t, const int* __restrict__ list,
    const float* __restrict__ attr_in, float* __restrict__ attr_out,
    float* __restrict__ spk, const float* __restrict__ gbase, long gstride,
    const float* __restrict__ WencT, const float* __restrict__ benc,
    const float* __restrict__ WrecT, const float* __restrict__ brec)
{
    __shared__ double red[8];
    const int n = min(*cnt_t, LIST_MAX);
    const int tid = threadIdx.x;
    for (int item = blockIdx.x; item < n; item += gridDim.x) {
        const int packed = list[item];
        const long elem = (long)(packed >> 1);
        const float s_old = (float)(packed & 1);
        const long row = elem / H_;
        const int  h   = (int)(elem % H_);
        const float* grow = gbase + row * gstride;
        const float* arow = attr_in + row * H_;
        const float* we = WencT + (long)h * H_;
        const float* wr = WrecT + (long)h * H_;
        double d = 0.0;
        for (int kk = tid; kk < H_; kk += 256)
            d += (double)grow[kk] * (double)we[kk]
               + (double)arow[kk] * (double)wr[kk];
        double w = d;
#pragma unroll
        for (int o = 16; o > 0; o >>= 1)
            w += __shfl_xor_sync(0xffffffffu, w, o);
        if ((tid & 31) == 0) red[tid >> 5] = w;
        __syncthreads();
        if (tid == 0) {
            double acc = (double)benc[h] + (double)brec[h];
#pragma unroll
            for (int q = 0; q < 8; q++) acc += red[q];
            float av_old = attr_in[elem];
            float v = av_old + ((float)acc - av_old) * 0.5f;
            float s_new = (v > 1.0f) ? 1.0f : 0.0f;
            attr_out[elem] = v - s_new;
            spk[elem] += (s_new - s_old);
        }
        __syncthreads();
    }
}

__global__ void __launch_bounds__(256) r17_init_kernel(
    float* __restrict__ attr, float* __restrict__ spk, int* __restrict__ cnt)
{
    long i = (long)blockIdx.x * blockDim.x + threadIdx.x;
    if (i < T_) cnt[i] = 0;
    float4 z = make_float4(0.f, 0.f, 0.f, 0.f);
    ((float4*)attr)[i] = z; ((float4*)spk)[i] = z;
}

__global__ void __launch_bounds__(256) r17_tail_kernel(
    const float* __restrict__ recall, const float* __restrict__ attr,
    float* __restrict__ out)
{
    long i = (long)blockIdx.x * blockDim.x + threadIdx.x;
    long e4 = i * 4;
    long b = e4 / H_;
    long h = e4 % H_;
    float4 rv = *(const float4*)(recall + ((long)b * T_ + (T_ - 1)) * H_ + h);
    ((float4*)out)[i] = rv;
    ((float4*)(out + (long)B_ * H_))[i] = ((const float4*)attr)[i];
}

// ==================== launch =================================================
#define GETSYM(var, sym) cudaGetSymbolAddress((void**)&var, sym)

extern "C" void kernel_launch(void* const* d_in, const int* in_sizes, int n_in,
                              void* d_out, int out_size)
{
    const float* x    = (const float*)d_in[0];
    const float* Wp   = (const float*)d_in[1];
    const float* bp   = (const float*)d_in[2];
    const float* Wfc  = (const float*)d_in[3];
    const float* bfc  = (const float*)d_in[4];
    const float* gamma= (const float*)d_in[5];
    const float* beta = (const float*)d_in[6];
    const float* Wg   = (const float*)d_in[7];
    const float* bg   = (const float*)d_in[8];
    const float* Wenc = (const float*)d_in[9];
    const float* benc = (const float*)d_in[10];
    const float* Wrec = (const float*)d_in[11];
    const float* brec = (const float*)d_in[12];
    const float* Wro  = (const float*)d_in[13];
    const float* bro  = (const float*)d_in[14];
    float* out = (float*)d_out;

    float *Wfused, *bfused, *WencT, *WrecT;
    float *preall, *sall, *recall, *ctxall, *gatedall, *encall;
    float *attrA, *attrB, *spk;
    int *cnt, *list;
    GETSYM(Wfused, r17_Wfused);   GETSYM(bfused, r17_bfused);
    GETSYM(WencT, r17_WencT);     GETSYM(WrecT, r17_WrecT);
    GETSYM(preall, r17_preall);   GETSYM(sall, r17_sall);
    GETSYM(recall, r17_recall);   GETSYM(ctxall, r17_ctxall);
    GETSYM(gatedall, r17_gatedall); GETSYM(encall, r17_encall);
    GETSYM(attrA, r17_attrA);     GETSYM(attrB, r17_attrB);
    GETSYM(spk, r17_spk);
    GETSYM(cnt, r17_cnt);         GETSYM(list, r17_list);

    const int EW = (B_ * H_ / 4) / 256;
    const dim3 gbig(H_ / 128, (B_ * T_) / 128);
    const dim3 gstep(H_ / 128, B_ / 128);

    r17_init_kernel<<<EW, 256>>>(attrA, spk, cnt);

    // prep
    r17_sgemm<<<dim3(H_ / 128, D_ / 128), 256>>>(
        0, Wp, H_, Wfc, nullptr, nullptr, nullptr, 0,
        nullptr, nullptr, nullptr, nullptr,
        Wfused, H_, D_, H_, H_, 1.0f);
    r17_bfused_kernel<<<H_ / 256, 256>>>(bp, Wfc, bfc, bfused);
    r17_transpose_kernel<<<dim3(H_ / 32, H_ / 32), 256>>>(Wenc, WencT, H_, H_);
    r17_transpose_kernel<<<dim3(H_ / 32, H_ / 32), 256>>>(Wrec, WrecT, H_, H_);

    // preall = x @ Wfused + bfused
    r17_sgemm<<<gbig, 256>>>(
        0, x, D_, Wfused, bfused, nullptr, nullptr, 0,
        nullptr, nullptr, nullptr, nullptr,
        preall, H_, B_ * T_, H_, D_, 1.0f);

    // rec chain (all t)
    r17_chain_kernel<<<B_, 256>>>(preall, recall, ctxall, sall, gamma, beta);

    // batched GEMM2 + fused gate: gatedall = sigmoid(sall@Wg+bg)*ctx + (1-g)*rec
    r17_sgemm<<<gbig, 256>>>(
        1, sall, H_, Wg, bg, nullptr, nullptr, 0,
        ctxall, recall, nullptr, nullptr,
        gatedall, H_, B_ * T_, H_, H_, 1.0f);

    // batched enc half: encall = gatedall @ Wenc + benc + brec
    r17_sgemm<<<gbig, 256>>>(
        0, gatedall, H_, Wenc, benc, brec, nullptr, 0,
        nullptr, nullptr, nullptr, nullptr,
        encall, H_, B_ * T_, H_, H_, 1.0f);

    // sequential attr recurrence with fused LIF epilogue
    for (int t = 0; t < T_; t++) {
        float* attr_in  = (t & 1) ? attrB : attrA;
        float* attr_out = (t & 1) ? attrA : attrB;
        r17_sgemm<<<gstep, 256>>>(
            2, attr_in, H_, Wrec, nullptr, nullptr,
            encall + (long)t * H_, (long)T_ * H_,
            attr_in, spk, cnt + t, list,
            attr_out, H_, B_, H_, H_, 1.0f);
        r17_refine_kernel<<<232, 256>>>(cnt + t, list, attr_in, attr_out, spk,
                                        gatedall + (long)t * H_, (long)T_ * H_,
                                        WencT, benc, WrecT, brec);
    }

    // readout
    r17_sgemm<<<dim3(O_ / 128, B_ / 128), 256>>>(
        0, spk, H_, Wro, bro, nullptr, nullptr, 0,
        nullptr, nullptr, nullptr, nullptr,
        out, O_, B_, O_, H_, 1.0f / 16.0f);
    r17_tail_kernel<<<EW, 256>>>(recall, attrA, out + (long)B_ * O_);
}